// round 12
// baseline (speedup 1.0000x reference)
#include <cuda_runtime.h>

// AdvectionDiffusionReaction2M — single persistent kernel, tile-local sync.
// R4/R11 body (ext 64x64, owned 48x48, 4x4 cells/thread, S=8) unchanged.
// 121 blocks (all co-resident on 148 SMs) each keep one tile for all 25
// chunks; inter-chunk dependency is only the 3x3 tile neighborhood, enforced
// with per-tile monotone flags (release-publish / acquire-poll). Flags are
// never reset: each run reads its own flag as `base` (uniform at entry since
// every run adds exactly 25), making graph replays safe.
// Core threads (cells fully inside the owned 48x48) carry registers across
// chunks — their post-fixup values equal gmem — so only the 112 halo-ring
// threads reload per chunk.

#define NN     512
#define N2     (NN * NN)
#define S      8
#define TILEW  48
#define EXT    64
#define NB     11          // 11x11 tiles
#define NCHUNK 25          // 24x8 + 1x7 = 199 steps

__device__ int g_flags[NB * NB];   // zero-initialized; monotone across replays

__device__ __forceinline__ int ld_acquire_gpu(const int* p) {
    int v;
    asm volatile("ld.acquire.gpu.u32 %0, [%1];" : "=r"(v) : "l"(p) : "memory");
    return v;
}
__device__ __forceinline__ void st_release_gpu(int* p, int v) {
    asm volatile("st.release.gpu.u32 [%0], %1;" :: "l"(p), "r"(v) : "memory");
}

__global__ __launch_bounds__(256)
void adr_persist_kernel(const float* __restrict__ u0,
                        float*       __restrict__ out,
                        const float* __restrict__ k1p,
                        const float* __restrict__ k2p,
                        const float* __restrict__ a1p,
                        const float* __restrict__ a2p)
{
    __shared__ float s_top[2][18][EXT];
    __shared__ float s_bot[2][18][EXT];
    __shared__ int   s_base;

    const int tx = threadIdx.x;   // 0..15
    const int ty = threadIdx.y;   // 0..15
    const int bx = blockIdx.x;    // 0..10
    const int by = blockIdx.y;    // 0..10
    const int bid = by * NB + bx;

    const int ro0 = by * TILEW;
    const int co0 = bx * TILEW;
    const int gi0 = ro0 - S + 4 * ty;
    const int gj0 = co0 - S + 4 * tx;

    // ---- epoch base (own flag; uniform across blocks at kernel entry) ----
    if (tx == 0 && ty == 0) s_base = g_flags[bid];

    // ---- neighbor list (up to 8), one poller thread per neighbor ----
    int my_nbr = -1;
    {
        const int ltid = ty * 16 + tx;
        int cnt = 0;
        #pragma unroll
        for (int dy = -1; dy <= 1; ++dy)
            #pragma unroll
            for (int dx = -1; dx <= 1; ++dx) {
                if (dx == 0 && dy == 0) continue;
                const int nx = bx + dx, ny = by + dy;
                if (nx < 0 || nx >= NB || ny < 0 || ny >= NB) continue;
                if (cnt == ltid) my_nbr = ny * NB + nx;
                ++cnt;
            }
    }

    const float k1 = __ldg(k1p), k2 = __ldg(k2p);
    const float a1 = __ldg(a1p), a2 = __ldg(a2p);
    const float inv_ksum = 1.0f / (k1 + k2);

    const float dx2f   = (float)((1.0 / 511.0) * (1.0 / 511.0));
    const float twodxf = (float)(2.0 / 511.0);
    const float DT     = 1e-7f;

    const float kap  = (gj0 < 256) ? k1 : k2;
    const float al   = (gj0 < 256) ? a1 : a2;
    const float c_al = DT * al / dx2f;
    const float cx   = DT * kap / twodxf;
    const float ck   = DT * kap;

    const bool ifc      = (gj0 + 3 == 255);
    const bool fix_rt   = (by == 0        && ty == 2);
    const bool fix_rb   = (ro0 == 480     && ty == 9);
    const bool fix_cl   = (bx == 0        && tx == 2);
    const bool fix_cr   = (co0 == 480     && tx == 9);
    const bool core     = (tx >= 2 && tx < 14 && ty >= 2 && ty < 14);
    const bool store_ok = core && (gi0 < NN) && (gj0 < NN);

    const unsigned FULL = 0xffffffffu;

    __syncthreads();                    // s_base visible
    const int base = s_base;

    float v[4][4];

    for (int chunk = 0; chunk < NCHUNK; ++chunk) {
        const int t0   = 8 * chunk;
        const int nlev = (chunk == NCHUNK - 1) ? 7 : 8;

        // ---- wait for 3x3 neighborhood to finish chunk-1 ----
        if (chunk > 0) {
            if (my_nbr >= 0) {
                const int target = base + chunk;
                while (ld_acquire_gpu(&g_flags[my_nbr]) < target) { }
            }
            __syncthreads();            // all threads ordered after acquires
        }

        // ---- (re)load: chunk 0 everyone from u0; later only halo-ring threads ----
        if (chunk == 0 || !core) {
            const float* __restrict__ src =
                (chunk == 0) ? u0 : (out + (size_t)(t0 - 1) * N2);
            #pragma unroll
            for (int r = 0; r < 4; ++r) {
                const int gi = min(max(gi0 + r, 0), NN - 1);
                #pragma unroll
                for (int c = 0; c < 4; ++c) {
                    const int gj = min(max(gj0 + c, 0), NN - 1);
                    v[r][c] = src[gi * NN + gj];
                }
            }
        }

        float* __restrict__ slab = out + (size_t)t0 * N2;

        #pragma unroll
        for (int k = 0; k < 8; ++k) {
            if (k >= nlev) break;
            const int pb = k & 1;

            // ---- vertical boundary exchange (old values, 16B ops) ----
            *(float4*)&s_top[pb][ty + 1][4 * tx] = make_float4(v[0][0], v[0][1], v[0][2], v[0][3]);
            *(float4*)&s_bot[pb][ty + 1][4 * tx] = make_float4(v[3][0], v[3][1], v[3][2], v[3][3]);
            __syncthreads();
            const float4 upv = *(const float4*)&s_bot[pb][ty][4 * tx];
            const float4 dnv = *(const float4*)&s_top[pb][ty + 2][4 * tx];
            const float up[4] = {upv.x, upv.y, upv.z, upv.w};
            const float dn[4] = {dnv.x, dnv.y, dnv.z, dnv.w};

            // ---- horizontal pack edges ----
            float lft[4], rgt[4];
            #pragma unroll
            for (int r = 0; r < 4; ++r) {
                lft[r] = __shfl_up_sync(FULL,   v[r][3], 1);
                rgt[r] = __shfl_down_sync(FULL, v[r][0], 1);
            }

            // ---- 16 cell updates (identical arithmetic to R4/R11) ----
            float n[4][4];
            #pragma unroll
            for (int r = 0; r < 4; ++r) {
                #pragma unroll
                for (int c = 0; c < 4; ++c) {
                    const float cu = v[r][c];
                    const float u_ = (r == 0) ? up[c] : v[r - 1][c];
                    const float d_ = (r == 3) ? dn[c] : v[r + 1][c];
                    const float l_ = (c == 0) ? lft[r] : v[r][c - 1];
                    const float r_ = (c == 3) ? rgt[r] : v[r][c + 1];

                    const float sum  = (u_ + d_) + (l_ + r_);
                    const float lap  = fmaf(-4.0f, cu, sum);
                    const float A    = fmaf(cu, d_ - u_, l_ - r_);
                    const float adv  = cu * A;
                    const float q    = fmaf(cu, cu, -cu);
                    const float reac = cu * (q + 1.0f);

                    float val = fmaf(c_al, lap, cu);
                    val = fmaf(-cx, adv, val);
                    val = fmaf(ck, reac, val);
                    n[r][c] = val;
                }
            }

            // ---- interface column j=255, from OLD neighbors ----
            if (ifc) {
                #pragma unroll
                for (int r = 0; r < 4; ++r)
                    n[r][3] = (k1 * rgt[r] + k2 * v[r][2]) * inv_ksum;
            }

            // ---- domain-edge fixups ----
            if (fix_rt) { n[0][0] = n[1][0]; n[0][1] = n[1][1]; n[0][2] = n[1][2]; n[0][3] = n[1][3]; }
            if (fix_rb) { n[3][0] = n[2][0]; n[3][1] = n[2][1]; n[3][2] = n[2][2]; n[3][3] = n[2][3]; }
            if (fix_cl) { n[0][0] = n[0][1]; n[1][0] = n[1][1]; n[2][0] = n[2][1]; n[3][0] = n[3][1]; }
            if (fix_cr) { n[0][3] = n[0][2]; n[1][3] = n[1][2]; n[2][3] = n[2][2]; n[3][3] = n[3][2]; }

            // ---- store owned 4x4 ----
            if (store_ok) {
                #pragma unroll
                for (int r = 0; r < 4; ++r)
                    *(float4*)&slab[(size_t)(gi0 + r) * NN + gj0] =
                        make_float4(n[r][0], n[r][1], n[r][2], n[r][3]);
            }

            slab += N2;
            #pragma unroll
            for (int r = 0; r < 4; ++r)
                #pragma unroll
                for (int c = 0; c < 4; ++c)
                    v[r][c] = n[r][c];
        }

        // ---- publish chunk completion (release) ----
        __threadfence();                 // each thread's STGs gpu-visible
        __syncthreads();                 // all threads fenced before flag
        if (tx == 0 && ty == 0)
            st_release_gpu(&g_flags[bid], base + chunk + 1);
    }
}

extern "C" void kernel_launch(void* const* d_in, const int* in_sizes, int n_in,
                              void* d_out, int out_size)
{
    const float* u0  = (const float*)d_in[0];
    const float* k1p = (const float*)d_in[1];
    const float* k2p = (const float*)d_in[2];
    const float* a1p = (const float*)d_in[3];
    const float* a2p = (const float*)d_in[4];
    float* out = (float*)d_out;

    dim3 block(16, 16, 1);
    dim3 grid(NB, NB, 1);   // 121 blocks <= 148 SMs: all co-resident, wave 1

    adr_persist_kernel<<<grid, block>>>(u0, out, k1p, k2p, a1p, a2p);
}

// round 13
// speedup vs baseline: 1.2243x; 1.2243x over previous
#include <cuda_runtime.h>

// AdvectionDiffusionReaction2M — R11 champion (temporal-blocked stencil,
// ext 64x64 / owned 48x48 / 4x4 cells/thread / S=8 / 25 PDL-chained launches)
// with the PDL trigger moved to KERNEL ENTRY.
// R12 lesson: in-kernel neighbor-flag sync serializes fences+polls on the
// critical path (245us). Instead, deepen the launch pipeline: triggering at
// entry lets up to ~4 successor grids become resident and park at
// griddepcontrol.wait (HW-sleep), so each boundary costs ~wakeup+loads
// instead of a full launch ramp. Grid k+1 still gridsyncs on grid k before
// reading src — correctness identical.

#define NN     512
#define N2     (NN * NN)
#define S      8
#define TILEW  48
#define EXT    64
#define NSTEPS 199

template <int NS>
__global__ __launch_bounds__(256)
void adr_chunk_kernel(const float* __restrict__ src,
                      float*       __restrict__ out,
                      int t0,
                      const float* __restrict__ k1p,
                      const float* __restrict__ k2p,
                      const float* __restrict__ a1p,
                      const float* __restrict__ a2p)
{
    // ---- permit the dependent grid to launch immediately ----
    cudaTriggerProgrammaticLaunchCompletion();

    // double-buffered strip-boundary rows; strip ty+1, pads at 0 and 17
    __shared__ float s_top[2][18][EXT];
    __shared__ float s_bot[2][18][EXT];

    const int tx = threadIdx.x;   // 0..15, cols 4tx..4tx+3 of ext tile
    const int ty = threadIdx.y;   // 0..15, rows 4ty..4ty+3

    const int ro0 = blockIdx.y * TILEW;
    const int co0 = blockIdx.x * TILEW;
    const int gi0 = ro0 - S + 4 * ty;
    const int gj0 = co0 - S + 4 * tx;

    // -------- prologue independent of the producer chunk --------
    const float k1 = __ldg(k1p), k2 = __ldg(k2p);
    const float a1 = __ldg(a1p), a2 = __ldg(a2p);
    const float inv_ksum = 1.0f / (k1 + k2);

    const float dx2f   = (float)((1.0 / 511.0) * (1.0 / 511.0));
    const float twodxf = (float)(2.0 / 511.0);
    const float DT     = 1e-7f;

    // 4-col packs never straddle j=256
    const float kap  = (gj0 < 256) ? k1 : k2;
    const float al   = (gj0 < 256) ? a1 : a2;
    const float c_al = DT * al / dx2f;
    const float cx   = DT * kap / twodxf;
    const float ck   = DT * kap;

    // fixup / ownership flags (validated rounds 4/11)
    const bool ifc      = (gj0 + 3 == 255);
    const bool fix_rt   = (blockIdx.y == 0  && ty == 2);   // row 0   <- row 1
    const bool fix_rb   = (ro0 == 480       && ty == 9);   // row 511 <- row 510
    const bool fix_cl   = (blockIdx.x == 0  && tx == 2);   // col 0   <- col 1
    const bool fix_cr   = (co0 == 480       && tx == 9);   // col 511 <- col 510
    const bool store_ok = (tx >= 2 && tx < 14 && ty >= 2 && ty < 14 &&
                           gi0 < NN && gj0 < NN);

    const unsigned FULL = 0xffffffffu;

    // -------- wait for the producer grid to fully complete --------
    cudaGridDependencySynchronize();

    // ---- clamped initial load (field at step t0-1) ----
    float v[4][4];
    #pragma unroll
    for (int r = 0; r < 4; ++r) {
        const int gi = min(max(gi0 + r, 0), NN - 1);
        #pragma unroll
        for (int c = 0; c < 4; ++c) {
            const int gj = min(max(gj0 + c, 0), NN - 1);
            v[r][c] = src[gi * NN + gj];
        }
    }

    float* __restrict__ slab = out + (size_t)t0 * N2;

    #pragma unroll
    for (int k = 0; k < NS; ++k) {
        const int pb = k & 1;

        // ---- vertical boundary exchange (old values, 16B ops) ----
        *(float4*)&s_top[pb][ty + 1][4 * tx] = make_float4(v[0][0], v[0][1], v[0][2], v[0][3]);
        *(float4*)&s_bot[pb][ty + 1][4 * tx] = make_float4(v[3][0], v[3][1], v[3][2], v[3][3]);
        __syncthreads();
        const float4 upv = *(const float4*)&s_bot[pb][ty][4 * tx];       // row above strip
        const float4 dnv = *(const float4*)&s_top[pb][ty + 2][4 * tx];   // row below strip
        const float up[4] = {upv.x, upv.y, upv.z, upv.w};
        const float dn[4] = {dnv.x, dnv.y, dnv.z, dnv.w};

        // ---- horizontal pack edges (old values) ----
        float lft[4], rgt[4];
        #pragma unroll
        for (int r = 0; r < 4; ++r) {
            lft[r] = __shfl_up_sync(FULL,   v[r][3], 1);
            rgt[r] = __shfl_down_sync(FULL, v[r][0], 1);
        }

        // ---- 16 cell updates ----
        float n[4][4];
        #pragma unroll
        for (int r = 0; r < 4; ++r) {
            #pragma unroll
            for (int c = 0; c < 4; ++c) {
                const float cu = v[r][c];
                const float u_ = (r == 0) ? up[c] : v[r - 1][c];
                const float d_ = (r == 3) ? dn[c] : v[r + 1][c];
                const float l_ = (c == 0) ? lft[r] : v[r][c - 1];
                const float r_ = (c == 3) ? rgt[r] : v[r][c + 1];

                const float sum  = (u_ + d_) + (l_ + r_);
                const float lap  = fmaf(-4.0f, cu, sum);
                const float A    = fmaf(cu, d_ - u_, l_ - r_);
                const float adv  = cu * A;
                const float q    = fmaf(cu, cu, -cu);
                const float reac = cu * (q + 1.0f);

                float val = fmaf(c_al, lap, cu);
                val = fmaf(-cx, adv, val);
                val = fmaf(ck, reac, val);
                n[r][c] = val;
            }
        }

        // ---- interface column j=255 (c==3 of tx==5), from OLD neighbors ----
        if (ifc) {
            #pragma unroll
            for (int r = 0; r < 4; ++r)
                n[r][3] = (k1 * rgt[r] + k2 * v[r][2]) * inv_ksum;
        }

        // ---- domain-edge fixups (rows then cols, matching reference order) ----
        if (fix_rt) { n[0][0] = n[1][0]; n[0][1] = n[1][1]; n[0][2] = n[1][2]; n[0][3] = n[1][3]; }
        if (fix_rb) { n[3][0] = n[2][0]; n[3][1] = n[2][1]; n[3][2] = n[2][2]; n[3][3] = n[2][3]; }
        if (fix_cl) { n[0][0] = n[0][1]; n[1][0] = n[1][1]; n[2][0] = n[2][1]; n[3][0] = n[3][1]; }
        if (fix_cr) { n[0][3] = n[0][2]; n[1][3] = n[1][2]; n[2][3] = n[2][2]; n[3][3] = n[3][2]; }

        // ---- store owned 4x4 (coalesced 16B stores) ----
        if (store_ok) {
            #pragma unroll
            for (int r = 0; r < 4; ++r)
                *(float4*)&slab[(size_t)(gi0 + r) * NN + gj0] =
                    make_float4(n[r][0], n[r][1], n[r][2], n[r][3]);
        }

        slab += N2;
        #pragma unroll
        for (int r = 0; r < 4; ++r)
            #pragma unroll
            for (int c = 0; c < 4; ++c)
                v[r][c] = n[r][c];
    }
}

template <int NS>
static void launch_chunk(const float* src, float* out, int t0,
                         const float* k1p, const float* k2p,
                         const float* a1p, const float* a2p)
{
    dim3 block(16, 16, 1);
    dim3 grid((NN + TILEW - 1) / TILEW, (NN + TILEW - 1) / TILEW, 1);  // 11 x 11

    cudaLaunchAttribute attr[1];
    attr[0].id = cudaLaunchAttributeProgrammaticStreamSerialization;
    attr[0].val.programmaticStreamSerializationAllowed = 1;

    cudaLaunchConfig_t cfg = {};
    cfg.gridDim = grid;
    cfg.blockDim = block;
    cfg.dynamicSmemBytes = 0;
    cfg.stream = 0;
    cfg.attrs = attr;
    cfg.numAttrs = 1;

    cudaLaunchKernelEx(&cfg, adr_chunk_kernel<NS>,
                       src, out, t0, k1p, k2p, a1p, a2p);
}

extern "C" void kernel_launch(void* const* d_in, const int* in_sizes, int n_in,
                              void* d_out, int out_size)
{
    const float* u0  = (const float*)d_in[0];
    const float* k1p = (const float*)d_in[1];
    const float* k2p = (const float*)d_in[2];
    const float* a1p = (const float*)d_in[3];
    const float* a2p = (const float*)d_in[4];
    float* out = (float*)d_out;

    int t0 = 0;
    for (int c = 0; c < 24; ++c) {
        const float* src = (t0 == 0) ? u0 : (out + (size_t)(t0 - 1) * N2);
        launch_chunk<8>(src, out, t0, k1p, k2p, a1p, a2p);
        t0 += 8;
    }
    {
        const float* src = out + (size_t)(t0 - 1) * N2;
        launch_chunk<7>(src, out, t0, k1p, k2p, a1p, a2p);
    }
}

// round 14
// speedup vs baseline: 2.1582x; 1.7629x over previous
#include <cuda_runtime.h>

// AdvectionDiffusionReaction2M — R11 champion structure (ext 64x64, owned
// 48x48, 4x4 cells/thread, S=8, 25 PDL launches, trigger AFTER level 0 —
// R13 proved entry-trigger regresses) with a Horner-form cell update:
//   out = A1*s + c*(B0 + A2*(l-r)) + c^2*(A2*(d-u) - ck) + c^3*ck
//   B0 = 1 - 4*c_al + ck,  A2 = -cx,  s = (u+d)+(l+r)
// 11 FP ops/cell (was 14) and vA/vB register ping-pong removes the per-level
// v<-n copies. Everything else byte-identical to R11.

#define NN     512
#define N2     (NN * NN)
#define S      8
#define TILEW  48
#define EXT    64
#define NSTEPS 199

template <int NS>
__global__ __launch_bounds__(256)
void adr_chunk_kernel(const float* __restrict__ src,
                      float*       __restrict__ out,
                      int t0,
                      const float* __restrict__ k1p,
                      const float* __restrict__ k2p,
                      const float* __restrict__ a1p,
                      const float* __restrict__ a2p)
{
    __shared__ float s_top[2][18][EXT];
    __shared__ float s_bot[2][18][EXT];

    const int tx = threadIdx.x;   // 0..15, cols 4tx..4tx+3 of ext tile
    const int ty = threadIdx.y;   // 0..15, rows 4ty..4ty+3

    const int ro0 = blockIdx.y * TILEW;
    const int co0 = blockIdx.x * TILEW;
    const int gi0 = ro0 - S + 4 * ty;
    const int gj0 = co0 - S + 4 * tx;

    // -------- prologue independent of the producer chunk --------
    const float k1 = __ldg(k1p), k2 = __ldg(k2p);
    const float a1 = __ldg(a1p), a2 = __ldg(a2p);
    const float inv_ksum = 1.0f / (k1 + k2);

    const float dx2f   = (float)((1.0 / 511.0) * (1.0 / 511.0));
    const float twodxf = (float)(2.0 / 511.0);
    const float DT     = 1e-7f;

    // 4-col packs never straddle j=256
    const float kap  = (gj0 < 256) ? k1 : k2;
    const float al   = (gj0 < 256) ? a1 : a2;
    const float c_al = DT * al / dx2f;
    const float cx   = DT * kap / twodxf;
    const float ck   = DT * kap;

    // Horner coefficients
    const float A1  = c_al;
    const float A2  = -cx;
    const float B0  = 1.0f - 4.0f * c_al + ck;
    const float mA3 = -ck;      // -ck
    const float A3  = ck;

    const bool ifc      = (gj0 + 3 == 255);
    const bool fix_rt   = (blockIdx.y == 0  && ty == 2);   // row 0   <- row 1
    const bool fix_rb   = (ro0 == 480       && ty == 9);   // row 511 <- row 510
    const bool fix_cl   = (blockIdx.x == 0  && tx == 2);   // col 0   <- col 1
    const bool fix_cr   = (co0 == 480       && tx == 9);   // col 511 <- col 510
    const bool store_ok = (tx >= 2 && tx < 14 && ty >= 2 && ty < 14 &&
                           gi0 < NN && gj0 < NN);

    const unsigned FULL = 0xffffffffu;

    // -------- wait for the producer grid to fully complete --------
    cudaGridDependencySynchronize();

    float vA[4][4], vB[4][4];
    #pragma unroll
    for (int r = 0; r < 4; ++r) {
        const int gi = min(max(gi0 + r, 0), NN - 1);
        #pragma unroll
        for (int c = 0; c < 4; ++c) {
            const int gj = min(max(gj0 + c, 0), NN - 1);
            vA[r][c] = src[gi * NN + gj];
        }
    }

    // ---- one temporal level: v -> n, store owned cells into slab ----
    auto do_level = [&](float (&v)[4][4], float (&n)[4][4], int pb,
                        float* __restrict__ slab) {
        // vertical boundary exchange (old values, 16B ops)
        *(float4*)&s_top[pb][ty + 1][4 * tx] = make_float4(v[0][0], v[0][1], v[0][2], v[0][3]);
        *(float4*)&s_bot[pb][ty + 1][4 * tx] = make_float4(v[3][0], v[3][1], v[3][2], v[3][3]);
        __syncthreads();
        const float4 upv = *(const float4*)&s_bot[pb][ty][4 * tx];
        const float4 dnv = *(const float4*)&s_top[pb][ty + 2][4 * tx];
        const float up[4] = {upv.x, upv.y, upv.z, upv.w};
        const float dn[4] = {dnv.x, dnv.y, dnv.z, dnv.w};

        // horizontal pack edges (old values)
        float lft[4], rgt[4];
        #pragma unroll
        for (int r = 0; r < 4; ++r) {
            lft[r] = __shfl_up_sync(FULL,   v[r][3], 1);
            rgt[r] = __shfl_down_sync(FULL, v[r][0], 1);
        }

        // 16 cell updates, Horner form
        #pragma unroll
        for (int r = 0; r < 4; ++r) {
            #pragma unroll
            for (int c = 0; c < 4; ++c) {
                const float cu = v[r][c];
                const float u_ = (r == 0) ? up[c] : v[r - 1][c];
                const float d_ = (r == 3) ? dn[c] : v[r + 1][c];
                const float l_ = (c == 0) ? lft[r] : v[r][c - 1];
                const float r_ = (c == 3) ? rgt[r] : v[r][c + 1];

                const float sum = (u_ + d_) + (l_ + r_);
                const float P0  = A1 * sum;
                const float du  = d_ - u_;
                const float lr  = l_ - r_;
                const float T1  = fmaf(A2, lr, B0);
                const float T2  = fmaf(A2, du, mA3);
                float h = fmaf(cu, A3, T2);
                h = fmaf(cu, h, T1);
                n[r][c] = fmaf(cu, h, P0);
            }
        }

        // interface column j=255 (c==3 of tx==5), from OLD neighbors
        if (ifc) {
            #pragma unroll
            for (int r = 0; r < 4; ++r)
                n[r][3] = (k1 * rgt[r] + k2 * v[r][2]) * inv_ksum;
        }

        // domain-edge fixups (rows then cols, matching reference order)
        if (fix_rt) { n[0][0] = n[1][0]; n[0][1] = n[1][1]; n[0][2] = n[1][2]; n[0][3] = n[1][3]; }
        if (fix_rb) { n[3][0] = n[2][0]; n[3][1] = n[2][1]; n[3][2] = n[2][2]; n[3][3] = n[2][3]; }
        if (fix_cl) { n[0][0] = n[0][1]; n[1][0] = n[1][1]; n[2][0] = n[2][1]; n[3][0] = n[3][1]; }
        if (fix_cr) { n[0][3] = n[0][2]; n[1][3] = n[1][2]; n[2][3] = n[2][2]; n[3][3] = n[3][2]; }

        // store owned 4x4 (coalesced 16B stores)
        if (store_ok) {
            #pragma unroll
            for (int r = 0; r < 4; ++r)
                *(float4*)&slab[(size_t)(gi0 + r) * NN + gj0] =
                    make_float4(n[r][0], n[r][1], n[r][2], n[r][3]);
        }
    };

    float* slab = out + (size_t)t0 * N2;

    // level 0, then permit dependent launch (R11-validated placement)
    do_level(vA, vB, 0, slab);
    slab += N2;
    cudaTriggerProgrammaticLaunchCompletion();

    // levels 1..NS-1 with register ping-pong (no v<-n copies)
    #pragma unroll
    for (int k = 1; k < NS; ++k) {
        if (k & 1) do_level(vB, vA, 1, slab);
        else       do_level(vA, vB, 0, slab);
        slab += N2;
    }
}

template <int NS>
static void launch_chunk(const float* src, float* out, int t0,
                         const float* k1p, const float* k2p,
                         const float* a1p, const float* a2p)
{
    dim3 block(16, 16, 1);
    dim3 grid((NN + TILEW - 1) / TILEW, (NN + TILEW - 1) / TILEW, 1);  // 11 x 11

    cudaLaunchAttribute attr[1];
    attr[0].id = cudaLaunchAttributeProgrammaticStreamSerialization;
    attr[0].val.programmaticStreamSerializationAllowed = 1;

    cudaLaunchConfig_t cfg = {};
    cfg.gridDim = grid;
    cfg.blockDim = block;
    cfg.dynamicSmemBytes = 0;
    cfg.stream = 0;
    cfg.attrs = attr;
    cfg.numAttrs = 1;

    cudaLaunchKernelEx(&cfg, adr_chunk_kernel<NS>,
                       src, out, t0, k1p, k2p, a1p, a2p);
}

extern "C" void kernel_launch(void* const* d_in, const int* in_sizes, int n_in,
                              void* d_out, int out_size)
{
    const float* u0  = (const float*)d_in[0];
    const float* k1p = (const float*)d_in[1];
    const float* k2p = (const float*)d_in[2];
    const float* a1p = (const float*)d_in[3];
    const float* a2p = (const float*)d_in[4];
    float* out = (float*)d_out;

    int t0 = 0;
    for (int c = 0; c < 24; ++c) {
        const float* src = (t0 == 0) ? u0 : (out + (size_t)(t0 - 1) * N2);
        launch_chunk<8>(src, out, t0, k1p, k2p, a1p, a2p);
        t0 += 8;
    }
    {
        const float* src = out + (size_t)(t0 - 1) * N2;
        launch_chunk<7>(src, out, t0, k1p, k2p, a1p, a2p);
    }
}

// round 15
// speedup vs baseline: 2.2631x; 1.0486x over previous
#include <cuda_runtime.h>

// AdvectionDiffusionReaction2M — R14 champion (Horner cell update, ext 64x64,
// owned 48x48, 4x4 cells/thread, S=8, 25 PDL launches, trigger after level 0)
// with chunk-entry critical path shaved:
//   1) interior threads load 4x LDG.128 instead of 16x LDG.32
//   2) boundary rows (0,3) loaded first and STS'd; interior rows (1,2) load
//      during the barrier wait
//   3) __launch_bounds__(256,1) for register/scheduling headroom
// R13: trigger placement frozen at after-level-0. R12: no in-kernel sync.

#define NN     512
#define N2     (NN * NN)
#define S      8
#define TILEW  48
#define EXT    64
#define NSTEPS 199

template <int NS>
__global__ __launch_bounds__(256, 1)
void adr_chunk_kernel(const float* __restrict__ src,
                      float*       __restrict__ out,
                      int t0,
                      const float* __restrict__ k1p,
                      const float* __restrict__ k2p,
                      const float* __restrict__ a1p,
                      const float* __restrict__ a2p)
{
    __shared__ float s_top[2][18][EXT];
    __shared__ float s_bot[2][18][EXT];

    const int tx = threadIdx.x;   // 0..15, cols 4tx..4tx+3 of ext tile
    const int ty = threadIdx.y;   // 0..15, rows 4ty..4ty+3

    const int ro0 = blockIdx.y * TILEW;
    const int co0 = blockIdx.x * TILEW;
    const int gi0 = ro0 - S + 4 * ty;
    const int gj0 = co0 - S + 4 * tx;

    // -------- prologue independent of the producer chunk --------
    const float k1 = __ldg(k1p), k2 = __ldg(k2p);
    const float a1 = __ldg(a1p), a2 = __ldg(a2p);
    const float inv_ksum = 1.0f / (k1 + k2);

    const float dx2f   = (float)((1.0 / 511.0) * (1.0 / 511.0));
    const float twodxf = (float)(2.0 / 511.0);
    const float DT     = 1e-7f;

    const float kap  = (gj0 < 256) ? k1 : k2;
    const float al   = (gj0 < 256) ? a1 : a2;
    const float c_al = DT * al / dx2f;
    const float cx   = DT * kap / twodxf;
    const float ck   = DT * kap;

    // Horner coefficients (R14-validated)
    const float A1  = c_al;
    const float A2  = -cx;
    const float B0  = 1.0f - 4.0f * c_al + ck;
    const float mA3 = -ck;
    const float A3  = ck;

    const bool ifc      = (gj0 + 3 == 255);
    const bool fix_rt   = (blockIdx.y == 0  && ty == 2);
    const bool fix_rb   = (ro0 == 480       && ty == 9);
    const bool fix_cl   = (blockIdx.x == 0  && tx == 2);
    const bool fix_cr   = (co0 == 480       && tx == 9);
    const bool store_ok = (tx >= 2 && tx < 14 && ty >= 2 && ty < 14 &&
                           gi0 < NN && gj0 < NN);
    const bool vec_ld   = (gj0 >= 0) && (gj0 <= NN - 4);   // 4-col pack in-range

    const unsigned FULL = 0xffffffffu;

    // -------- wait for the producer grid to fully complete --------
    cudaGridDependencySynchronize();

    float vA[4][4], vB[4][4];

    // ---- boundary rows first (feed the level-0 STS immediately) ----
    {
        const int gib0 = min(max(gi0 + 0, 0), NN - 1);
        const int gib3 = min(max(gi0 + 3, 0), NN - 1);
        if (vec_ld) {
            const float4 p0 = *(const float4*)&src[(size_t)gib0 * NN + gj0];
            const float4 p3 = *(const float4*)&src[(size_t)gib3 * NN + gj0];
            vA[0][0] = p0.x; vA[0][1] = p0.y; vA[0][2] = p0.z; vA[0][3] = p0.w;
            vA[3][0] = p3.x; vA[3][1] = p3.y; vA[3][2] = p3.z; vA[3][3] = p3.w;
        } else {
            #pragma unroll
            for (int c = 0; c < 4; ++c) {
                const int gj = min(max(gj0 + c, 0), NN - 1);
                vA[0][c] = src[(size_t)gib0 * NN + gj];
                vA[3][c] = src[(size_t)gib3 * NN + gj];
            }
        }
    }
    // STS level-0 boundary rows now; interior rows load during the bar wait
    *(float4*)&s_top[0][ty + 1][4 * tx] = make_float4(vA[0][0], vA[0][1], vA[0][2], vA[0][3]);
    *(float4*)&s_bot[0][ty + 1][4 * tx] = make_float4(vA[3][0], vA[3][1], vA[3][2], vA[3][3]);
    {
        const int gib1 = min(max(gi0 + 1, 0), NN - 1);
        const int gib2 = min(max(gi0 + 2, 0), NN - 1);
        if (vec_ld) {
            const float4 p1 = *(const float4*)&src[(size_t)gib1 * NN + gj0];
            const float4 p2 = *(const float4*)&src[(size_t)gib2 * NN + gj0];
            vA[1][0] = p1.x; vA[1][1] = p1.y; vA[1][2] = p1.z; vA[1][3] = p1.w;
            vA[2][0] = p2.x; vA[2][1] = p2.y; vA[2][2] = p2.z; vA[2][3] = p2.w;
        } else {
            #pragma unroll
            for (int c = 0; c < 4; ++c) {
                const int gj = min(max(gj0 + c, 0), NN - 1);
                vA[1][c] = src[(size_t)gib1 * NN + gj];
                vA[2][c] = src[(size_t)gib2 * NN + gj];
            }
        }
    }

    // ---- one temporal level: v -> n; sts_done: STS already performed ----
    auto do_level = [&](float (&v)[4][4], float (&n)[4][4], int pb,
                        float* __restrict__ slab, bool sts_done) {
        if (!sts_done) {
            *(float4*)&s_top[pb][ty + 1][4 * tx] = make_float4(v[0][0], v[0][1], v[0][2], v[0][3]);
            *(float4*)&s_bot[pb][ty + 1][4 * tx] = make_float4(v[3][0], v[3][1], v[3][2], v[3][3]);
        }
        __syncthreads();
        const float4 upv = *(const float4*)&s_bot[pb][ty][4 * tx];
        const float4 dnv = *(const float4*)&s_top[pb][ty + 2][4 * tx];
        const float up[4] = {upv.x, upv.y, upv.z, upv.w};
        const float dn[4] = {dnv.x, dnv.y, dnv.z, dnv.w};

        float lft[4], rgt[4];
        #pragma unroll
        for (int r = 0; r < 4; ++r) {
            lft[r] = __shfl_up_sync(FULL,   v[r][3], 1);
            rgt[r] = __shfl_down_sync(FULL, v[r][0], 1);
        }

        #pragma unroll
        for (int r = 0; r < 4; ++r) {
            #pragma unroll
            for (int c = 0; c < 4; ++c) {
                const float cu = v[r][c];
                const float u_ = (r == 0) ? up[c] : v[r - 1][c];
                const float d_ = (r == 3) ? dn[c] : v[r + 1][c];
                const float l_ = (c == 0) ? lft[r] : v[r][c - 1];
                const float r_ = (c == 3) ? rgt[r] : v[r][c + 1];

                const float sum = (u_ + d_) + (l_ + r_);
                const float P0  = A1 * sum;
                const float du  = d_ - u_;
                const float lr  = l_ - r_;
                const float T1  = fmaf(A2, lr, B0);
                const float T2  = fmaf(A2, du, mA3);
                float h = fmaf(cu, A3, T2);
                h = fmaf(cu, h, T1);
                n[r][c] = fmaf(cu, h, P0);
            }
        }

        if (ifc) {
            #pragma unroll
            for (int r = 0; r < 4; ++r)
                n[r][3] = (k1 * rgt[r] + k2 * v[r][2]) * inv_ksum;
        }

        if (fix_rt) { n[0][0] = n[1][0]; n[0][1] = n[1][1]; n[0][2] = n[1][2]; n[0][3] = n[1][3]; }
        if (fix_rb) { n[3][0] = n[2][0]; n[3][1] = n[2][1]; n[3][2] = n[2][2]; n[3][3] = n[2][3]; }
        if (fix_cl) { n[0][0] = n[0][1]; n[1][0] = n[1][1]; n[2][0] = n[2][1]; n[3][0] = n[3][1]; }
        if (fix_cr) { n[0][3] = n[0][2]; n[1][3] = n[1][2]; n[2][3] = n[2][2]; n[3][3] = n[3][2]; }

        if (store_ok) {
            #pragma unroll
            for (int r = 0; r < 4; ++r)
                *(float4*)&slab[(size_t)(gi0 + r) * NN + gj0] =
                    make_float4(n[r][0], n[r][1], n[r][2], n[r][3]);
        }
    };

    float* slab = out + (size_t)t0 * N2;

    // level 0 (STS already done above), then permit dependent launch
    do_level(vA, vB, 0, slab, true);
    slab += N2;
    cudaTriggerProgrammaticLaunchCompletion();

    #pragma unroll
    for (int k = 1; k < NS; ++k) {
        if (k & 1) do_level(vB, vA, 1, slab, false);
        else       do_level(vA, vB, 0, slab, false);
        slab += N2;
    }
}

template <int NS>
static void launch_chunk(const float* src, float* out, int t0,
                         const float* k1p, const float* k2p,
                         const float* a1p, const float* a2p)
{
    dim3 block(16, 16, 1);
    dim3 grid((NN + TILEW - 1) / TILEW, (NN + TILEW - 1) / TILEW, 1);  // 11 x 11

    cudaLaunchAttribute attr[1];
    attr[0].id = cudaLaunchAttributeProgrammaticStreamSerialization;
    attr[0].val.programmaticStreamSerializationAllowed = 1;

    cudaLaunchConfig_t cfg = {};
    cfg.gridDim = grid;
    cfg.blockDim = block;
    cfg.dynamicSmemBytes = 0;
    cfg.stream = 0;
    cfg.attrs = attr;
    cfg.numAttrs = 1;

    cudaLaunchKernelEx(&cfg, adr_chunk_kernel<NS>,
                       src, out, t0, k1p, k2p, a1p, a2p);
}

extern "C" void kernel_launch(void* const* d_in, const int* in_sizes, int n_in,
                              void* d_out, int out_size)
{
    const float* u0  = (const float*)d_in[0];
    const float* k1p = (const float*)d_in[1];
    const float* k2p = (const float*)d_in[2];
    const float* a1p = (const float*)d_in[3];
    const float* a2p = (const float*)d_in[4];
    float* out = (float*)d_out;

    int t0 = 0;
    for (int c = 0; c < 24; ++c) {
        const float* src = (t0 == 0) ? u0 : (out + (size_t)(t0 - 1) * N2);
        launch_chunk<8>(src, out, t0, k1p, k2p, a1p, a2p);
        t0 += 8;
    }
    {
        const float* src = out + (size_t)(t0 - 1) * N2;
        launch_chunk<7>(src, out, t0, k1p, k2p, a1p, a2p);
    }
}